// round 13
// baseline (speedup 1.0000x reference)
#include <cuda_runtime.h>
#include <cuda_bf16.h>
#include <stdint.h>
#include <cstdint>
#include <math.h>

#define T_STEPS 64
#define BATCH   1024
#define OBSD    8
#define HID     512
#define TB      (T_STEPS * BATCH)   /* 65536 */
#define GATE3   (3 * HID)           /* 1536  */

typedef __nv_bfloat16 bf16;

// ---------------- fp32 state ------------------------------------------------
__device__ __align__(128) float g_H   [TB * HID];
__device__ __align__(128) float g_KACC[TB * HID];
__device__ __align__(128) float g_GI  [(size_t)TB * GATE3];
__device__ __align__(128) float g_GH  [3 * BATCH * GATE3];   // 3 plane partials
__device__ __align__(128) float g_HP0 [BATCH * HID];
__device__ __align__(128) float g_HP1 [BATCH * HID];

// ---------------- bf16 hi/lo activation planes ------------------------------
__device__ __align__(128) bf16 g_Hh [TB * HID], g_Hl [TB * HID];
__device__ __align__(128) bf16 g_Th [TB * HID], g_Tl [TB * HID];
__device__ __align__(128) bf16 g_Z1h[TB * HID], g_Z1l[TB * HID];
__device__ __align__(128) bf16 g_Z2h[TB * HID], g_Z2l[TB * HID];
__device__ __align__(128) bf16 g_P0h[BATCH * HID], g_P0l[BATCH * HID];
__device__ __align__(128) bf16 g_P1h[BATCH * HID], g_P1l[BATCH * HID];

// ---------------- bf16 hi/lo weight planes [K, N] row-major ------------------
__device__ __align__(128) bf16 g_W1h[HID * HID],   g_W1l[HID * HID];
__device__ __align__(128) bf16 g_W2h[HID * HID],   g_W2l[HID * HID];
__device__ __align__(128) bf16 g_Woh[HID * HID],   g_Wol[HID * HID];
__device__ __align__(128) bf16 g_Wih_h[HID * GATE3], g_Wih_l[HID * GATE3];
__device__ __align__(128) bf16 g_Whh_h[HID * GATE3], g_Whh_l[HID * GATE3];

// ---------------- helpers ----------------------------------------------------
__device__ __forceinline__ void store_planes(bf16* __restrict__ ph,
                                             bf16* __restrict__ pl,
                                             size_t idx, float a, float b) {
    bf16 ah = __float2bfloat16(a);
    bf16 bh = __float2bfloat16(b);
    float ar = a - __bfloat162float(ah);
    float br = b - __bfloat162float(bh);
    __nv_bfloat162 vh; vh.x = ah; vh.y = bh;
    __nv_bfloat162 vl; vl.x = __float2bfloat16(ar); vl.y = __float2bfloat16(br);
    *reinterpret_cast<__nv_bfloat162*>(ph + idx) = vh;
    *reinterpret_cast<__nv_bfloat162*>(pl + idx) = vl;
}

__device__ __forceinline__ void mma16816(float* d, const unsigned* a, const unsigned* b) {
    asm volatile(
        "mma.sync.aligned.m16n8k16.row.col.f32.bf16.bf16.f32 "
        "{%0,%1,%2,%3},{%4,%5,%6,%7},{%8,%9},{%0,%1,%2,%3};\n"
        : "+f"(d[0]), "+f"(d[1]), "+f"(d[2]), "+f"(d[3])
        : "r"(a[0]), "r"(a[1]), "r"(a[2]), "r"(a[3]), "r"(b[0]), "r"(b[1]));
}

__device__ __forceinline__ void ldsm4(unsigned* r, uint32_t addr) {
    asm volatile("ldmatrix.sync.aligned.m8n8.x4.shared.b16 {%0,%1,%2,%3},[%4];\n"
                 : "=r"(r[0]), "=r"(r[1]), "=r"(r[2]), "=r"(r[3]) : "r"(addr));
}
__device__ __forceinline__ void ldsm4t(unsigned* r, uint32_t addr) {
    asm volatile("ldmatrix.sync.aligned.m8n8.x4.trans.shared.b16 {%0,%1,%2,%3},[%4];\n"
                 : "=r"(r[0]), "=r"(r[1]), "=r"(r[2]), "=r"(r[3]) : "r"(addr));
}
__device__ __forceinline__ void cp16(uint32_t d, const void* s) {
    asm volatile("cp.async.cg.shared.global [%0], [%1], 16;\n" :: "r"(d), "l"(s));
}
__device__ __forceinline__ void cp_commit() {
    asm volatile("cp.async.commit_group;\n" ::: "memory");
}

// ---------------- weight split ----------------------------------------------
__global__ void split_kernel(const float* __restrict__ src,
                             bf16* __restrict__ hi, bf16* __restrict__ lo, int n) {
    int i = blockIdx.x * blockDim.x + threadIdx.x;
    if (i < n) {
        float x = src[i];
        bf16 h = __float2bfloat16(x);
        hi[i] = h;
        lo[i] = __float2bfloat16(x - __bfloat162float(h));
    }
}

__global__ void zero_hp0_kernel() {
    int i = blockIdx.x * blockDim.x + threadIdx.x;
    if (i < BATCH * HID) {
        g_HP0[i] = 0.f;
        g_P0h[i] = __float2bfloat16(0.f);
        g_P0l[i] = __float2bfloat16(0.f);
    }
}

// ---------------- obs -> hidden ----------------------------------------------
__global__ void obs_kernel(const float* __restrict__ xs,
                           const float* __restrict__ W,
                           const float* __restrict__ b,
                           const float* __restrict__ lng,
                           const float* __restrict__ lnb) {
    int row = blockIdx.x;
    int tid = threadIdx.x;
    __shared__ float xrow[OBSD];
    if (tid < OBSD) xrow[tid] = xs[row * OBSD + tid];
    __syncthreads();

    float y[2];
#pragma unroll
    for (int j = 0; j < 2; j++) {
        int c = tid + j * 256;
        float acc = b[c];
#pragma unroll
        for (int k = 0; k < OBSD; k++) acc += xrow[k] * W[k * HID + c];
        y[j] = acc;
    }
    float s = y[0] + y[1];
    float ss = y[0] * y[0] + y[1] * y[1];
#pragma unroll
    for (int o = 16; o > 0; o >>= 1) {
        s  += __shfl_xor_sync(0xffffffffu, s, o);
        ss += __shfl_xor_sync(0xffffffffu, ss, o);
    }
    __shared__ float rs[8], rss[8];
    int warp = tid >> 5, lane = tid & 31;
    if (lane == 0) { rs[warp] = s; rss[warp] = ss; }
    __syncthreads();
    if (warp == 0) {
        float a  = (lane < 8) ? rs[lane]  : 0.f;
        float b2 = (lane < 8) ? rss[lane] : 0.f;
#pragma unroll
        for (int o = 4; o > 0; o >>= 1) {
            a  += __shfl_xor_sync(0xffffffffu, a, o);
            b2 += __shfl_xor_sync(0xffffffffu, b2, o);
        }
        if (lane == 0) { rs[0] = a; rss[0] = b2; }
    }
    __syncthreads();
    float mean = rs[0] * (1.f / HID);
    float var  = rss[0] * (1.f / HID) - mean * mean;
    float inv  = rsqrtf(var + 1e-5f);
#pragma unroll
    for (int j = 0; j < 2; j++) {
        int c = tid + j * 256;
        float v = (y[j] - mean) * inv * lng[c] + lnb[c];
        v = v > 0.f ? v : 0.01f * v;
        size_t idx = (size_t)row * HID + c;
        g_H[idx] = v;
        bf16 h = __float2bfloat16(v);
        g_Hh[idx] = h;
        g_Hl[idx] = __float2bfloat16(v - __bfloat162float(h));
    }
}

// ---------------- tensor-core GEMM: M=64/CTA, 512 thr, 4-stage pipeline ------
// Warp grid 4x4. Normal mode: all 3 split products per chunk (12 MMAs/g2).
// splitZ mode: blockIdx.z selects ONE product plane (0:Ah*Bh 1:Ah*Bl 2:Al*Bh);
// CTA loads only that plane (into the p=0 slots) and issues 4 MMAs/g2; output
// goes to a per-plane partial buffer (out += z * BATCH * ldo).
// modes: 0 = LN+leaky -> planes; 1 = fp32 out; 2..5 = RK4 epilogues.
#define A_STAGE     6144                 /* 2 planes * 64 rows * 24 * 2B */
#define STAGE_BYTES 39424                /* A_STAGE + 2*16*520*2        */
#define NSTAGE      4
#define SMEM_TOTAL_BYTES (NSTAGE * STAGE_BYTES)

__device__ __forceinline__ void load_stage(uint32_t smb, int buf, int k0,
                                           const bf16* Ah, const bf16* Al,
                                           const bf16* Wh, const bf16* Wl,
                                           int ldw, int coff, int rowBase, int tid,
                                           int planeSel) {
    uint32_t aoff = smb + buf * STAGE_BYTES;
    uint32_t boff = aoff + A_STAGE;
    if (planeSel < 0) {
#pragma unroll
        for (int l = 0; l < 4; l++) {
            int idx = tid + l * 512;          // 0..2047
            int p   = idx >> 10;
            int rem = idx & 1023;
            int kr  = rem >> 6;
            int u   = rem & 63;
            const bf16* src = (p ? Wl : Wh) + (size_t)(k0 + kr) * ldw + coff + u * 8;
            cp16(boff + ((p * 16 + kr) * 520 + u * 8) * 2, src);
        }
        if (tid < 256) {
            int p   = tid >> 7;
            int rem = tid & 127;
            int r   = rem >> 1;
            int u   = rem & 1;
            const bf16* src = (p ? Al : Ah) + (size_t)(rowBase + r) * HID + k0 + u * 8;
            cp16(aoff + ((p * 64 + r) * 24 + u * 8) * 2, src);
        }
    } else {
        const bf16* Bsrc = (planeSel == 1) ? Wl : Wh;
        const bf16* Asrc = (planeSel == 2) ? Al : Ah;
#pragma unroll
        for (int l = 0; l < 2; l++) {         // B plane 0 region: 1024 cp16
            int idx = tid + l * 512;
            int kr  = idx >> 6;
            int u   = idx & 63;
            cp16(boff + (kr * 520 + u * 8) * 2,
                 Bsrc + (size_t)(k0 + kr) * ldw + coff + u * 8);
        }
        if (tid < 128) {                      // A plane 0 region: 128 cp16
            int r = tid >> 1;
            int u = tid & 1;
            cp16(aoff + (r * 24 + u * 8) * 2,
                 Asrc + (size_t)(rowBase + r) * HID + k0 + u * 8);
        }
    }
}

extern __shared__ char dyn_sm[];

__global__ void __launch_bounds__(512, 1)
gemm_mma(const bf16* __restrict__ Ah, const bf16* __restrict__ Al,
         const bf16* __restrict__ Wh, const bf16* __restrict__ Wl, int ldw,
         const float* __restrict__ bias,
         const float* __restrict__ trow, float tval,
         const float* __restrict__ lng, const float* __restrict__ lnb,
         float* __restrict__ out, int ldo,
         bf16* __restrict__ outh, bf16* __restrict__ outl,
         float* __restrict__ Hb, float* __restrict__ KACCb,
         int mode, int splitZ) {
    int tid  = threadIdx.x;
    int w    = tid >> 5;
    int lane = tid & 31;
    int wr   = w >> 2;         // warp row 0..3  -> rows wr*16..wr*16+15
    int wc   = w & 3;          // warp col 0..3  -> cols wc*128..wc*128+127
    int g    = lane >> 2;
    int tig  = lane & 3;
    int rowBase = blockIdx.x * 64;
    int coff    = blockIdx.y * 512;
    int planeSel = splitZ ? (int)blockIdx.z : -1;
    if (splitZ) out += (size_t)blockIdx.z * BATCH * (size_t)ldo;

    uint32_t smb = (uint32_t)__cvta_generic_to_shared(dyn_sm);

    float acc[16][4];
#pragma unroll
    for (int j = 0; j < 16; j++)
#pragma unroll
        for (int q = 0; q < 4; q++) acc[j][q] = 0.f;

    const int NC = HID / 16;   // 32

    // prologue: stages 0,1,2
    load_stage(smb, 0, 0,  Ah, Al, Wh, Wl, ldw, coff, rowBase, tid, planeSel); cp_commit();
    load_stage(smb, 1, 16, Ah, Al, Wh, Wl, ldw, coff, rowBase, tid, planeSel); cp_commit();
    load_stage(smb, 2, 32, Ah, Al, Wh, Wl, ldw, coff, rowBase, tid, planeSel); cp_commit();

#pragma unroll 1
    for (int c = 0; c < NC; c++) {
        asm volatile("cp.async.wait_group 2;\n" ::: "memory");
        __syncthreads();
        if (c + 3 < NC)
            load_stage(smb, (c + 3) & 3, (c + 3) * 16, Ah, Al, Wh, Wl, ldw, coff,
                       rowBase, tid, planeSel);
        cp_commit();   // always commit: keeps group count uniform

        uint32_t aoff = smb + (c & 3) * STAGE_BYTES;
        uint32_t boff = aoff + A_STAGE;

        if (planeSel < 0) {
            unsigned af[2][4];
#pragma unroll
            for (int p = 0; p < 2; p++) {
                uint32_t ad = aoff + ((p * 64 + wr * 16 + (lane & 15)) * 24 + (lane >> 4) * 8) * 2;
                ldsm4(af[p], ad);
            }
#pragma unroll
            for (int g2 = 0; g2 < 4; g2++) {
                unsigned bh0[4], bh1[4], bl0[4], bl1[4];
                uint32_t bd0 = boff + ((lane & 15) * 520 + wc * 128 + (g2 * 2) * 16 + (lane >> 4) * 8) * 2;
                uint32_t bd1 = bd0 + 32;
                ldsm4t(bh0, bd0);
                ldsm4t(bh1, bd1);
                ldsm4t(bl0, bd0 + 16 * 520 * 2);
                ldsm4t(bl1, bd1 + 16 * 520 * 2);
                int j0 = g2 * 4;
                mma16816(acc[j0 + 0], af[0], bh0);
                mma16816(acc[j0 + 1], af[0], bh0 + 2);
                mma16816(acc[j0 + 2], af[0], bh1);
                mma16816(acc[j0 + 3], af[0], bh1 + 2);
                mma16816(acc[j0 + 0], af[0], bl0);
                mma16816(acc[j0 + 1], af[0], bl0 + 2);
                mma16816(acc[j0 + 2], af[0], bl1);
                mma16816(acc[j0 + 3], af[0], bl1 + 2);
                mma16816(acc[j0 + 0], af[1], bh0);
                mma16816(acc[j0 + 1], af[1], bh0 + 2);
                mma16816(acc[j0 + 2], af[1], bh1);
                mma16816(acc[j0 + 3], af[1], bh1 + 2);
            }
        } else {
            unsigned af0[4];
            {
                uint32_t ad = aoff + ((wr * 16 + (lane & 15)) * 24 + (lane >> 4) * 8) * 2;
                ldsm4(af0, ad);
            }
#pragma unroll
            for (int g2 = 0; g2 < 4; g2++) {
                unsigned bh0[4], bh1[4];
                uint32_t bd0 = boff + ((lane & 15) * 520 + wc * 128 + (g2 * 2) * 16 + (lane >> 4) * 8) * 2;
                uint32_t bd1 = bd0 + 32;
                ldsm4t(bh0, bd0);
                ldsm4t(bh1, bd1);
                int j0 = g2 * 4;
                mma16816(acc[j0 + 0], af0, bh0);
                mma16816(acc[j0 + 1], af0, bh0 + 2);
                mma16816(acc[j0 + 2], af0, bh1);
                mma16816(acc[j0 + 3], af0, bh1 + 2);
            }
        }
    }

    if (mode == 0) {
        // fused LayerNorm over full 512-col rows (4 warp-cols cooperate via smem)
        float* red = reinterpret_cast<float*>(dyn_sm);
        float s0 = 0.f, q0 = 0.f, s1 = 0.f, q1 = 0.f;
#pragma unroll
        for (int jt = 0; jt < 16; jt++) {
            int cl = wc * 128 + jt * 8 + 2 * tig;
            float b0 = bias[coff + cl], b1 = bias[coff + cl + 1];
            if (trow) { b0 += tval * trow[coff + cl]; b1 += tval * trow[coff + cl + 1]; }
            float f0 = acc[jt][0] + b0, f1 = acc[jt][1] + b1;
            float f2 = acc[jt][2] + b0, f3 = acc[jt][3] + b1;
            acc[jt][0] = f0; acc[jt][1] = f1; acc[jt][2] = f2; acc[jt][3] = f3;
            s0 += f0 + f1; q0 += f0 * f0 + f1 * f1;
            s1 += f2 + f3; q1 += f2 * f2 + f3 * f3;
        }
#pragma unroll
        for (int o = 1; o <= 2; o <<= 1) {
            s0 += __shfl_xor_sync(0xffffffffu, s0, o);
            q0 += __shfl_xor_sync(0xffffffffu, q0, o);
            s1 += __shfl_xor_sync(0xffffffffu, s1, o);
            q1 += __shfl_xor_sync(0xffffffffu, q1, o);
        }
        if (tig == 0) {
            int r0 = wr * 16 + g, r1 = wr * 16 + 8 + g;
            red[r0 * 4 + wc] = s0; red[256 + r0 * 4 + wc] = q0;
            red[r1 * 4 + wc] = s1; red[256 + r1 * 4 + wc] = q1;
        }
        __syncthreads();
        if (tid < 64) {
            float s = 0.f, q = 0.f;
#pragma unroll
            for (int k = 0; k < 4; k++) { s += red[tid * 4 + k]; q += red[256 + tid * 4 + k]; }
            float mean = s * (1.f / HID);
            float inv  = rsqrtf(q * (1.f / HID) - mean * mean + 1e-5f);
            red[512 + tid] = mean;
            red[576 + tid] = inv;
        }
        __syncthreads();
#pragma unroll
        for (int h = 0; h < 2; h++) {
            int lr = wr * 16 + h * 8 + g;
            float mean = red[512 + lr], inv = red[576 + lr];
            size_t base = (size_t)(rowBase + lr) * HID;
#pragma unroll
            for (int jt = 0; jt < 16; jt++) {
                int cl = wc * 128 + jt * 8 + 2 * tig;
                float v0 = (acc[jt][h * 2 + 0] - mean) * inv * lng[cl] + lnb[cl];
                float v1 = (acc[jt][h * 2 + 1] - mean) * inv * lng[cl + 1] + lnb[cl + 1];
                v0 = v0 > 0.f ? v0 : 0.01f * v0;
                v1 = v1 > 0.f ? v1 : 0.01f * v1;
                store_planes(outh, outl, base + cl, v0, v1);
            }
        }
    } else if (mode == 1) {
#pragma unroll
        for (int h = 0; h < 2; h++) {
            size_t base = (size_t)(rowBase + wr * 16 + h * 8 + g) * ldo + coff;
#pragma unroll
            for (int jt = 0; jt < 16; jt++) {
                int cl = wc * 128 + jt * 8 + 2 * tig;
                float b0 = bias ? bias[coff + cl]     : 0.f;
                float b1 = bias ? bias[coff + cl + 1] : 0.f;
                float2 v;
                v.x = acc[jt][h * 2 + 0] + b0;
                v.y = acc[jt][h * 2 + 1] + b1;
                *reinterpret_cast<float2*>(out + base + cl) = v;
            }
        }
    } else {
#pragma unroll
        for (int h = 0; h < 2; h++) {
            size_t base = (size_t)(rowBase + wr * 16 + h * 8 + g) * HID;
#pragma unroll
            for (int jt = 0; jt < 16; jt++) {
                int cl = wc * 128 + jt * 8 + 2 * tig;
                size_t idx = base + cl;
                float b0 = bias[coff + cl], b1 = bias[coff + cl + 1];
                float f0 = acc[jt][h * 2 + 0] + b0;
                float f1 = acc[jt][h * 2 + 1] + b1;
                float2 hv = *reinterpret_cast<const float2*>(Hb + idx);
                if (mode == 2) {
                    float2 ka; ka.x = f0; ka.y = f1;
                    *reinterpret_cast<float2*>(KACCb + idx) = ka;
                    store_planes(outh, outl, idx, hv.x + 0.125f * f0, hv.y + 0.125f * f1);
                } else if (mode == 3) {
                    float2 ka = *reinterpret_cast<const float2*>(KACCb + idx);
                    ka.x += 2.f * f0; ka.y += 2.f * f1;
                    *reinterpret_cast<float2*>(KACCb + idx) = ka;
                    store_planes(outh, outl, idx, hv.x + 0.125f * f0, hv.y + 0.125f * f1);
                } else if (mode == 4) {
                    float2 ka = *reinterpret_cast<const float2*>(KACCb + idx);
                    ka.x += 2.f * f0; ka.y += 2.f * f1;
                    *reinterpret_cast<float2*>(KACCb + idx) = ka;
                    store_planes(outh, outl, idx, hv.x + 0.25f * f0, hv.y + 0.25f * f1);
                } else {
                    float2 ka = *reinterpret_cast<const float2*>(KACCb + idx);
                    float n0 = hv.x + (0.25f / 6.f) * (ka.x + f0);
                    float n1 = hv.y + (0.25f / 6.f) * (ka.y + f1);
                    float2 hn; hn.x = n0; hn.y = n1;
                    *reinterpret_cast<float2*>(Hb + idx) = hn;
                    store_planes(outh, outl, idx, n0, n1);
                }
            }
        }
    }
}

// ---------------- GRU gate fusion (sums 3 GH plane partials + b_hh) ----------
__global__ void gates_kernel(int t, const float* __restrict__ hp,
                             const float* __restrict__ bhh,
                             float* __restrict__ hn,
                             bf16* __restrict__ hnh, bf16* __restrict__ hnl,
                             float* __restrict__ dout) {
    int idx = blockIdx.x * blockDim.x + threadIdx.x;
    if (idx >= BATCH * HID) return;
    int r = idx >> 9;
    int c = idx & 511;
    size_t gib = ((size_t)t * BATCH + r) * GATE3;
    size_t ghb = (size_t)r * GATE3;
    const size_t PS = (size_t)BATCH * GATE3;
    float ir = g_GI[gib + c], iz = g_GI[gib + c + HID], in_ = g_GI[gib + c + 2 * HID];
    float hr = g_GH[ghb + c]           + g_GH[PS + ghb + c]           + g_GH[2 * PS + ghb + c]           + bhh[c];
    float hz = g_GH[ghb + c + HID]     + g_GH[PS + ghb + c + HID]     + g_GH[2 * PS + ghb + c + HID]     + bhh[c + HID];
    float hnn= g_GH[ghb + c + 2 * HID] + g_GH[PS + ghb + c + 2 * HID] + g_GH[2 * PS + ghb + c + 2 * HID] + bhh[c + 2 * HID];
    float rg = 1.f / (1.f + expf(-(ir + hr)));
    float zg = 1.f / (1.f + expf(-(iz + hz)));
    float ng = tanhf(in_ + rg * hnn);
    float h  = hp[idx];
    float v  = (1.f - zg) * ng + zg * h;
    hn[idx] = v;
    bf16 vh = __float2bfloat16(v);
    hnh[idx] = vh;
    hnl[idx] = __float2bfloat16(v - __bfloat162float(vh));
    if (dout) dout[idx] = v;
}

// ---------------- host orchestration ----------------------------------------
extern "C" void kernel_launch(void* const* d_in, const int* in_sizes, int n_in,
                              void* d_out, int out_size) {
    const float* xs       = (const float*)d_in[0];
    const float* obs_W    = (const float*)d_in[1];
    const float* obs_b    = (const float*)d_in[2];
    const float* obs_ln_g = (const float*)d_in[3];
    const float* obs_ln_b = (const float*)d_in[4];
    const float* ode_W1   = (const float*)d_in[5];   // [513,512]
    const float* ode_b1   = (const float*)d_in[6];
    const float* ode_ln1g = (const float*)d_in[7];
    const float* ode_ln1b = (const float*)d_in[8];
    const float* ode_W2   = (const float*)d_in[9];
    const float* ode_b2   = (const float*)d_in[10];
    const float* ode_ln2g = (const float*)d_in[11];
    const float* ode_ln2b = (const float*)d_in[12];
    const float* ode_Wout = (const float*)d_in[13];
    const float* ode_bout = (const float*)d_in[14];
    const float* W_ih     = (const float*)d_in[15];  // [512,1536]
    const float* b_ih     = (const float*)d_in[16];
    const float* W_hh     = (const float*)d_in[17];
    const float* b_hh     = (const float*)d_in[18];

    float *pH, *pKACC, *pGI, *pGH, *pHP0, *pHP1;
    cudaGetSymbolAddress((void**)&pH,    g_H);
    cudaGetSymbolAddress((void**)&pKACC, g_KACC);
    cudaGetSymbolAddress((void**)&pGI,   g_GI);
    cudaGetSymbolAddress((void**)&pGH,   g_GH);
    cudaGetSymbolAddress((void**)&pHP0,  g_HP0);
    cudaGetSymbolAddress((void**)&pHP1,  g_HP1);

    bf16 *pHh, *pHl, *pTh, *pTl, *pZ1h, *pZ1l, *pZ2h, *pZ2l;
    bf16 *pP0h, *pP0l, *pP1h, *pP1l;
    bf16 *pW1h, *pW1l, *pW2h, *pW2l, *pWoh, *pWol, *pWihh, *pWihl, *pWhhh, *pWhhl;
    cudaGetSymbolAddress((void**)&pHh,  g_Hh);   cudaGetSymbolAddress((void**)&pHl,  g_Hl);
    cudaGetSymbolAddress((void**)&pTh,  g_Th);   cudaGetSymbolAddress((void**)&pTl,  g_Tl);
    cudaGetSymbolAddress((void**)&pZ1h, g_Z1h);  cudaGetSymbolAddress((void**)&pZ1l, g_Z1l);
    cudaGetSymbolAddress((void**)&pZ2h, g_Z2h);  cudaGetSymbolAddress((void**)&pZ2l, g_Z2l);
    cudaGetSymbolAddress((void**)&pP0h, g_P0h);  cudaGetSymbolAddress((void**)&pP0l, g_P0l);
    cudaGetSymbolAddress((void**)&pP1h, g_P1h);  cudaGetSymbolAddress((void**)&pP1l, g_P1l);
    cudaGetSymbolAddress((void**)&pW1h, g_W1h);  cudaGetSymbolAddress((void**)&pW1l, g_W1l);
    cudaGetSymbolAddress((void**)&pW2h, g_W2h);  cudaGetSymbolAddress((void**)&pW2l, g_W2l);
    cudaGetSymbolAddress((void**)&pWoh, g_Woh);  cudaGetSymbolAddress((void**)&pWol, g_Wol);
    cudaGetSymbolAddress((void**)&pWihh, g_Wih_h); cudaGetSymbolAddress((void**)&pWihl, g_Wih_l);
    cudaGetSymbolAddress((void**)&pWhhh, g_Whh_h); cudaGetSymbolAddress((void**)&pWhhl, g_Whh_l);

    cudaFuncSetAttribute(gemm_mma, cudaFuncAttributeMaxDynamicSharedMemorySize,
                         SMEM_TOTAL_BYTES);

    {
        int n = HID * HID;
        split_kernel<<<(n + 255) / 256, 256>>>(ode_W1,   pW1h, pW1l, n);
        split_kernel<<<(n + 255) / 256, 256>>>(ode_W2,   pW2h, pW2l, n);
        split_kernel<<<(n + 255) / 256, 256>>>(ode_Wout, pWoh, pWol, n);
        int m = HID * GATE3;
        split_kernel<<<(m + 255) / 256, 256>>>(W_ih, pWihh, pWihl, m);
        split_kernel<<<(m + 255) / 256, 256>>>(W_hh, pWhhh, pWhhl, m);
    }

    zero_hp0_kernel<<<(BATCH * HID + 255) / 256, 256>>>();
    obs_kernel<<<TB, 256>>>(xs, obs_W, obs_b, obs_ln_g, obs_ln_b);

    const float* trow = ode_W1 + (size_t)512 * 512;
    dim3 gOde(TB / 64, 1);
    const size_t SM = SMEM_TOTAL_BYTES;

    for (int s = 0; s < 4; s++) {
        float t0 = s * 0.25f;
        float tv[4] = {t0, t0 + 0.125f, t0 + 0.125f, t0 + 0.25f};
        int   km[4] = {2, 3, 4, 5};
        for (int e = 0; e < 4; e++) {
            const bf16* Ahh = (e == 0) ? pHh : pTh;
            const bf16* All = (e == 0) ? pHl : pTl;
            gemm_mma<<<gOde, 512, SM>>>(Ahh, All, pW1h, pW1l, HID,
                                        ode_b1, trow, tv[e], ode_ln1g, ode_ln1b,
                                        nullptr, 0, pZ1h, pZ1l, nullptr, nullptr, 0, 0);
            gemm_mma<<<gOde, 512, SM>>>(pZ1h, pZ1l, pW2h, pW2l, HID,
                                        ode_b2, nullptr, 0.f, ode_ln2g, ode_ln2b,
                                        nullptr, 0, pZ2h, pZ2l, nullptr, nullptr, 0, 0);
            // k4+combine (mode 5) writes the H planes (read by next k1 / GI GEMM)
            bf16* oh = (km[e] == 5) ? pHh : pTh;
            bf16* ol = (km[e] == 5) ? pHl : pTl;
            gemm_mma<<<gOde, 512, SM>>>(pZ2h, pZ2l, pWoh, pWol, HID,
                                        ode_bout, nullptr, 0.f, nullptr, nullptr,
                                        nullptr, 0, oh, ol, pH, pKACC, km[e], 0);
        }
    }

    // gi = h_ode @ W_ih + b_ih for all timesteps
    gemm_mma<<<dim3(TB / 64, 3), 512, SM>>>(pHh, pHl, pWihh, pWihl, GATE3,
                                            b_ih, nullptr, 0.f, nullptr, nullptr,
                                            pGI, GATE3, nullptr, nullptr,
                                            nullptr, nullptr, 1, 0);

    // sequential GRU — gh GEMM plane-split over blockIdx.z for full-chip width
    for (int t = 0; t < T_STEPS; t++) {
        float* hp = (t & 1) ? pHP1 : pHP0;
        float* hn = (t & 1) ? pHP0 : pHP1;
        bf16* hph = (t & 1) ? pP1h : pP0h;
        bf16* hpl = (t & 1) ? pP1l : pP0l;
        bf16* hnh = (t & 1) ? pP0h : pP1h;
        bf16* hnl = (t & 1) ? pP0l : pP1l;
        gemm_mma<<<dim3(BATCH / 64, 3, 3), 512, SM>>>(hph, hpl, pWhhh, pWhhl, GATE3,
                                                      nullptr, nullptr, 0.f, nullptr, nullptr,
                                                      pGH, GATE3, nullptr, nullptr,
                                                      nullptr, nullptr, 1, 1);
        gates_kernel<<<(BATCH * HID + 255) / 256, 256>>>(
            t, hp, b_hh, hn, hnh, hnl, (t == T_STEPS - 1) ? (float*)d_out : nullptr);
    }
}

// round 15
// speedup vs baseline: 1.5664x; 1.5664x over previous
#include <cuda_runtime.h>
#include <cuda_bf16.h>
#include <stdint.h>
#include <cstdint>
#include <math.h>

#define T_STEPS 64
#define BATCH   1024
#define OBSD    8
#define HID     512
#define TB      (T_STEPS * BATCH)   /* 65536 */
#define GATE3   (3 * HID)           /* 1536  */

typedef __nv_bfloat16 bf16;

// ---------------- fp32 state ------------------------------------------------
__device__ __align__(128) float g_H   [TB * HID];
__device__ __align__(128) float g_KACC[TB * HID];
__device__ __align__(128) float g_GI  [(size_t)TB * GATE3];
__device__ __align__(128) float g_GH  [3 * BATCH * GATE3];   // 3 plane partials
__device__ __align__(128) float g_HP0 [BATCH * HID];
__device__ __align__(128) float g_HP1 [BATCH * HID];

// ---------------- bf16 hi/lo activation planes ------------------------------
__device__ __align__(128) bf16 g_Hh [TB * HID], g_Hl [TB * HID];
__device__ __align__(128) bf16 g_Th [TB * HID], g_Tl [TB * HID];
__device__ __align__(128) bf16 g_Z1h[TB * HID], g_Z1l[TB * HID];
__device__ __align__(128) bf16 g_Z2h[TB * HID], g_Z2l[TB * HID];
__device__ __align__(128) bf16 g_P0h[BATCH * HID], g_P0l[BATCH * HID];
__device__ __align__(128) bf16 g_P1h[BATCH * HID], g_P1l[BATCH * HID];

// ---------------- bf16 hi/lo weight planes [K, N] row-major ------------------
__device__ __align__(128) bf16 g_W1h[HID * HID],   g_W1l[HID * HID];
__device__ __align__(128) bf16 g_W2h[HID * HID],   g_W2l[HID * HID];
__device__ __align__(128) bf16 g_Woh[HID * HID],   g_Wol[HID * HID];
__device__ __align__(128) bf16 g_Wih_h[HID * GATE3], g_Wih_l[HID * GATE3];
__device__ __align__(128) bf16 g_Whh_h[HID * GATE3], g_Whh_l[HID * GATE3];

// ---------------- helpers ----------------------------------------------------
__device__ __forceinline__ void store_planes(bf16* __restrict__ ph,
                                             bf16* __restrict__ pl,
                                             size_t idx, float a, float b) {
    bf16 ah = __float2bfloat16(a);
    bf16 bh = __float2bfloat16(b);
    float ar = a - __bfloat162float(ah);
    float br = b - __bfloat162float(bh);
    __nv_bfloat162 vh; vh.x = ah; vh.y = bh;
    __nv_bfloat162 vl; vl.x = __float2bfloat16(ar); vl.y = __float2bfloat16(br);
    *reinterpret_cast<__nv_bfloat162*>(ph + idx) = vh;
    *reinterpret_cast<__nv_bfloat162*>(pl + idx) = vl;
}

__device__ __forceinline__ void mma16816(float* d, const unsigned* a, const unsigned* b) {
    asm volatile(
        "mma.sync.aligned.m16n8k16.row.col.f32.bf16.bf16.f32 "
        "{%0,%1,%2,%3},{%4,%5,%6,%7},{%8,%9},{%0,%1,%2,%3};\n"
        : "+f"(d[0]), "+f"(d[1]), "+f"(d[2]), "+f"(d[3])
        : "r"(a[0]), "r"(a[1]), "r"(a[2]), "r"(a[3]), "r"(b[0]), "r"(b[1]));
}

__device__ __forceinline__ void ldsm4(unsigned* r, uint32_t addr) {
    asm volatile("ldmatrix.sync.aligned.m8n8.x4.shared.b16 {%0,%1,%2,%3},[%4];\n"
                 : "=r"(r[0]), "=r"(r[1]), "=r"(r[2]), "=r"(r[3]) : "r"(addr));
}
__device__ __forceinline__ void ldsm4t(unsigned* r, uint32_t addr) {
    asm volatile("ldmatrix.sync.aligned.m8n8.x4.trans.shared.b16 {%0,%1,%2,%3},[%4];\n"
                 : "=r"(r[0]), "=r"(r[1]), "=r"(r[2]), "=r"(r[3]) : "r"(addr));
}
__device__ __forceinline__ void cp16(uint32_t d, const void* s) {
    asm volatile("cp.async.cg.shared.global [%0], [%1], 16;\n" :: "r"(d), "l"(s));
}
__device__ __forceinline__ void cp_commit() {
    asm volatile("cp.async.commit_group;\n" ::: "memory");
}

// ---------------- weight split ----------------------------------------------
__global__ void split_kernel(const float* __restrict__ src,
                             bf16* __restrict__ hi, bf16* __restrict__ lo, int n) {
    int i = blockIdx.x * blockDim.x + threadIdx.x;
    if (i < n) {
        float x = src[i];
        bf16 h = __float2bfloat16(x);
        hi[i] = h;
        lo[i] = __float2bfloat16(x - __bfloat162float(h));
    }
}

__global__ void zero_hp0_kernel() {
    int i = blockIdx.x * blockDim.x + threadIdx.x;
    if (i < BATCH * HID) {
        g_HP0[i] = 0.f;
        g_P0h[i] = __float2bfloat16(0.f);
        g_P0l[i] = __float2bfloat16(0.f);
    }
}

// ---------------- obs -> hidden ----------------------------------------------
__global__ void obs_kernel(const float* __restrict__ xs,
                           const float* __restrict__ W,
                           const float* __restrict__ b,
                           const float* __restrict__ lng,
                           const float* __restrict__ lnb) {
    int row = blockIdx.x;
    int tid = threadIdx.x;
    __shared__ float xrow[OBSD];
    if (tid < OBSD) xrow[tid] = xs[row * OBSD + tid];
    __syncthreads();

    float y[2];
#pragma unroll
    for (int j = 0; j < 2; j++) {
        int c = tid + j * 256;
        float acc = b[c];
#pragma unroll
        for (int k = 0; k < OBSD; k++) acc += xrow[k] * W[k * HID + c];
        y[j] = acc;
    }
    float s = y[0] + y[1];
    float ss = y[0] * y[0] + y[1] * y[1];
#pragma unroll
    for (int o = 16; o > 0; o >>= 1) {
        s  += __shfl_xor_sync(0xffffffffu, s, o);
        ss += __shfl_xor_sync(0xffffffffu, ss, o);
    }
    __shared__ float rs[8], rss[8];
    int warp = tid >> 5, lane = tid & 31;
    if (lane == 0) { rs[warp] = s; rss[warp] = ss; }
    __syncthreads();
    if (warp == 0) {
        float a  = (lane < 8) ? rs[lane]  : 0.f;
        float b2 = (lane < 8) ? rss[lane] : 0.f;
#pragma unroll
        for (int o = 4; o > 0; o >>= 1) {
            a  += __shfl_xor_sync(0xffffffffu, a, o);
            b2 += __shfl_xor_sync(0xffffffffu, b2, o);
        }
        if (lane == 0) { rs[0] = a; rss[0] = b2; }
    }
    __syncthreads();
    float mean = rs[0] * (1.f / HID);
    float var  = rss[0] * (1.f / HID) - mean * mean;
    float inv  = rsqrtf(var + 1e-5f);
#pragma unroll
    for (int j = 0; j < 2; j++) {
        int c = tid + j * 256;
        float v = (y[j] - mean) * inv * lng[c] + lnb[c];
        v = v > 0.f ? v : 0.01f * v;
        size_t idx = (size_t)row * HID + c;
        g_H[idx] = v;
        bf16 h = __float2bfloat16(v);
        g_Hh[idx] = h;
        g_Hl[idx] = __float2bfloat16(v - __bfloat162float(h));
    }
}

// ---------------- tensor-core GEMM: M=64/CTA, 512 thr, 4-stage pipeline ------
// EXACT R11 kernel (21.4 ms champion) — no extra parameters, no branches.
#define A_STAGE     6144                 /* 2 planes * 64 rows * 24 * 2B */
#define STAGE_BYTES 39424                /* A_STAGE + 2*16*520*2        */
#define NSTAGE      4
#define SMEM_TOTAL_BYTES (NSTAGE * STAGE_BYTES)

__device__ __forceinline__ void load_stage(uint32_t smb, int buf, int k0,
                                           const bf16* Ah, const bf16* Al,
                                           const bf16* Wh, const bf16* Wl,
                                           int ldw, int coff, int rowBase, int tid) {
    uint32_t aoff = smb + buf * STAGE_BYTES;
    uint32_t boff = aoff + A_STAGE;
#pragma unroll
    for (int l = 0; l < 4; l++) {
        int idx = tid + l * 512;          // 0..2047
        int p   = idx >> 10;
        int rem = idx & 1023;
        int kr  = rem >> 6;
        int u   = rem & 63;
        const bf16* src = (p ? Wl : Wh) + (size_t)(k0 + kr) * ldw + coff + u * 8;
        cp16(boff + ((p * 16 + kr) * 520 + u * 8) * 2, src);
    }
    if (tid < 256) {
        int p   = tid >> 7;
        int rem = tid & 127;
        int r   = rem >> 1;
        int u   = rem & 1;
        const bf16* src = (p ? Al : Ah) + (size_t)(rowBase + r) * HID + k0 + u * 8;
        cp16(aoff + ((p * 64 + r) * 24 + u * 8) * 2, src);
    }
}

extern __shared__ char dyn_sm[];

__global__ void __launch_bounds__(512, 1)
gemm_mma(const bf16* __restrict__ Ah, const bf16* __restrict__ Al,
         const bf16* __restrict__ Wh, const bf16* __restrict__ Wl, int ldw,
         const float* __restrict__ bias,
         const float* __restrict__ trow, float tval,
         const float* __restrict__ lng, const float* __restrict__ lnb,
         float* __restrict__ out, int ldo,
         bf16* __restrict__ outh, bf16* __restrict__ outl,
         float* __restrict__ Hb, float* __restrict__ KACCb,
         int mode) {
    int tid  = threadIdx.x;
    int w    = tid >> 5;
    int lane = tid & 31;
    int wr   = w >> 2;
    int wc   = w & 3;
    int g    = lane >> 2;
    int tig  = lane & 3;
    int rowBase = blockIdx.x * 64;
    int coff    = blockIdx.y * 512;

    uint32_t smb = (uint32_t)__cvta_generic_to_shared(dyn_sm);

    float acc[16][4];
#pragma unroll
    for (int j = 0; j < 16; j++)
#pragma unroll
        for (int q = 0; q < 4; q++) acc[j][q] = 0.f;

    const int NC = HID / 16;   // 32

    load_stage(smb, 0, 0,  Ah, Al, Wh, Wl, ldw, coff, rowBase, tid); cp_commit();
    load_stage(smb, 1, 16, Ah, Al, Wh, Wl, ldw, coff, rowBase, tid); cp_commit();
    load_stage(smb, 2, 32, Ah, Al, Wh, Wl, ldw, coff, rowBase, tid); cp_commit();

#pragma unroll 1
    for (int c = 0; c < NC; c++) {
        asm volatile("cp.async.wait_group 2;\n" ::: "memory");
        __syncthreads();
        if (c + 3 < NC)
            load_stage(smb, (c + 3) & 3, (c + 3) * 16, Ah, Al, Wh, Wl, ldw, coff, rowBase, tid);
        cp_commit();

        uint32_t aoff = smb + (c & 3) * STAGE_BYTES;
        uint32_t boff = aoff + A_STAGE;

        unsigned af[2][4];
#pragma unroll
        for (int p = 0; p < 2; p++) {
            uint32_t ad = aoff + ((p * 64 + wr * 16 + (lane & 15)) * 24 + (lane >> 4) * 8) * 2;
            ldsm4(af[p], ad);
        }
#pragma unroll
        for (int g2 = 0; g2 < 4; g2++) {
            unsigned bh0[4], bh1[4], bl0[4], bl1[4];
            uint32_t bd0 = boff + ((lane & 15) * 520 + wc * 128 + (g2 * 2) * 16 + (lane >> 4) * 8) * 2;
            uint32_t bd1 = bd0 + 32;
            ldsm4t(bh0, bd0);
            ldsm4t(bh1, bd1);
            ldsm4t(bl0, bd0 + 16 * 520 * 2);
            ldsm4t(bl1, bd1 + 16 * 520 * 2);
            int j0 = g2 * 4;
            mma16816(acc[j0 + 0], af[0], bh0);
            mma16816(acc[j0 + 1], af[0], bh0 + 2);
            mma16816(acc[j0 + 2], af[0], bh1);
            mma16816(acc[j0 + 3], af[0], bh1 + 2);
            mma16816(acc[j0 + 0], af[0], bl0);
            mma16816(acc[j0 + 1], af[0], bl0 + 2);
            mma16816(acc[j0 + 2], af[0], bl1);
            mma16816(acc[j0 + 3], af[0], bl1 + 2);
            mma16816(acc[j0 + 0], af[1], bh0);
            mma16816(acc[j0 + 1], af[1], bh0 + 2);
            mma16816(acc[j0 + 2], af[1], bh1);
            mma16816(acc[j0 + 3], af[1], bh1 + 2);
        }
    }

    if (mode == 0) {
        float* red = reinterpret_cast<float*>(dyn_sm);
        float s0 = 0.f, q0 = 0.f, s1 = 0.f, q1 = 0.f;
#pragma unroll
        for (int jt = 0; jt < 16; jt++) {
            int cl = wc * 128 + jt * 8 + 2 * tig;
            float b0 = bias[coff + cl], b1 = bias[coff + cl + 1];
            if (trow) { b0 += tval * trow[coff + cl]; b1 += tval * trow[coff + cl + 1]; }
            float f0 = acc[jt][0] + b0, f1 = acc[jt][1] + b1;
            float f2 = acc[jt][2] + b0, f3 = acc[jt][3] + b1;
            acc[jt][0] = f0; acc[jt][1] = f1; acc[jt][2] = f2; acc[jt][3] = f3;
            s0 += f0 + f1; q0 += f0 * f0 + f1 * f1;
            s1 += f2 + f3; q1 += f2 * f2 + f3 * f3;
        }
#pragma unroll
        for (int o = 1; o <= 2; o <<= 1) {
            s0 += __shfl_xor_sync(0xffffffffu, s0, o);
            q0 += __shfl_xor_sync(0xffffffffu, q0, o);
            s1 += __shfl_xor_sync(0xffffffffu, s1, o);
            q1 += __shfl_xor_sync(0xffffffffu, q1, o);
        }
        if (tig == 0) {
            int r0 = wr * 16 + g, r1 = wr * 16 + 8 + g;
            red[r0 * 4 + wc] = s0; red[256 + r0 * 4 + wc] = q0;
            red[r1 * 4 + wc] = s1; red[256 + r1 * 4 + wc] = q1;
        }
        __syncthreads();
        if (tid < 64) {
            float s = 0.f, q = 0.f;
#pragma unroll
            for (int k = 0; k < 4; k++) { s += red[tid * 4 + k]; q += red[256 + tid * 4 + k]; }
            float mean = s * (1.f / HID);
            float inv  = rsqrtf(q * (1.f / HID) - mean * mean + 1e-5f);
            red[512 + tid] = mean;
            red[576 + tid] = inv;
        }
        __syncthreads();
#pragma unroll
        for (int h = 0; h < 2; h++) {
            int lr = wr * 16 + h * 8 + g;
            float mean = red[512 + lr], inv = red[576 + lr];
            size_t base = (size_t)(rowBase + lr) * HID;
#pragma unroll
            for (int jt = 0; jt < 16; jt++) {
                int cl = wc * 128 + jt * 8 + 2 * tig;
                float v0 = (acc[jt][h * 2 + 0] - mean) * inv * lng[cl] + lnb[cl];
                float v1 = (acc[jt][h * 2 + 1] - mean) * inv * lng[cl + 1] + lnb[cl + 1];
                v0 = v0 > 0.f ? v0 : 0.01f * v0;
                v1 = v1 > 0.f ? v1 : 0.01f * v1;
                store_planes(outh, outl, base + cl, v0, v1);
            }
        }
    } else if (mode == 1) {
#pragma unroll
        for (int h = 0; h < 2; h++) {
            size_t base = (size_t)(rowBase + wr * 16 + h * 8 + g) * ldo + coff;
#pragma unroll
            for (int jt = 0; jt < 16; jt++) {
                int cl = wc * 128 + jt * 8 + 2 * tig;
                float b0 = bias[coff + cl], b1 = bias[coff + cl + 1];
                float2 v;
                v.x = acc[jt][h * 2 + 0] + b0;
                v.y = acc[jt][h * 2 + 1] + b1;
                *reinterpret_cast<float2*>(out + base + cl) = v;
            }
        }
    } else {
#pragma unroll
        for (int h = 0; h < 2; h++) {
            size_t base = (size_t)(rowBase + wr * 16 + h * 8 + g) * HID;
#pragma unroll
            for (int jt = 0; jt < 16; jt++) {
                int cl = wc * 128 + jt * 8 + 2 * tig;
                size_t idx = base + cl;
                float b0 = bias[coff + cl], b1 = bias[coff + cl + 1];
                float f0 = acc[jt][h * 2 + 0] + b0;
                float f1 = acc[jt][h * 2 + 1] + b1;
                float2 hv = *reinterpret_cast<const float2*>(Hb + idx);
                if (mode == 2) {
                    float2 ka; ka.x = f0; ka.y = f1;
                    *reinterpret_cast<float2*>(KACCb + idx) = ka;
                    store_planes(outh, outl, idx, hv.x + 0.125f * f0, hv.y + 0.125f * f1);
                } else if (mode == 3) {
                    float2 ka = *reinterpret_cast<const float2*>(KACCb + idx);
                    ka.x += 2.f * f0; ka.y += 2.f * f1;
                    *reinterpret_cast<float2*>(KACCb + idx) = ka;
                    store_planes(outh, outl, idx, hv.x + 0.125f * f0, hv.y + 0.125f * f1);
                } else if (mode == 4) {
                    float2 ka = *reinterpret_cast<const float2*>(KACCb + idx);
                    ka.x += 2.f * f0; ka.y += 2.f * f1;
                    *reinterpret_cast<float2*>(KACCb + idx) = ka;
                    store_planes(outh, outl, idx, hv.x + 0.25f * f0, hv.y + 0.25f * f1);
                } else {
                    float2 ka = *reinterpret_cast<const float2*>(KACCb + idx);
                    float n0 = hv.x + (0.25f / 6.f) * (ka.x + f0);
                    float n1 = hv.y + (0.25f / 6.f) * (ka.y + f1);
                    float2 hn; hn.x = n0; hn.y = n1;
                    *reinterpret_cast<float2*>(Hb + idx) = hn;
                    store_planes(outh, outl, idx, n0, n1);
                }
            }
        }
    }
}

// ---------------- dedicated GRU plane-split GEMM -----------------------------
// blockIdx.z picks ONE product plane (0:Ah*Bh 1:Ah*Bl 2:Al*Bh). Grid (16,3,3)
// = 144 CTAs ~ one full wave. 1/3 the MMAs, ~1/2 the smem traffic per CTA.
// Output: plane partial at g_GH + z*BATCH*GATE3 (no bias; summed in gates).
__global__ void __launch_bounds__(512, 1)
gemm_gru(const bf16* __restrict__ Ah, const bf16* __restrict__ Al,
         const bf16* __restrict__ Wh, const bf16* __restrict__ Wl,
         float* __restrict__ out) {
    int tid  = threadIdx.x;
    int w    = tid >> 5;
    int lane = tid & 31;
    int wr   = w >> 2;
    int wc   = w & 3;
    int g    = lane >> 2;
    int tig  = lane & 3;
    int rowBase = blockIdx.x * 64;
    int coff    = blockIdx.y * 512;
    int plane   = blockIdx.z;
    out += (size_t)plane * BATCH * GATE3;
    const bf16* Ap = (plane == 2) ? Al : Ah;
    const bf16* Bp = (plane == 1) ? Wl : Wh;

    uint32_t smb = (uint32_t)__cvta_generic_to_shared(dyn_sm);

    float acc[16][4];
#pragma unroll
    for (int j = 0; j < 16; j++)
#pragma unroll
        for (int q = 0; q < 4; q++) acc[j][q] = 0.f;

    const int NC = HID / 16;

    // single-plane stage loader (A -> p=0 region, B -> p=0 region)
    auto load1 = [&](int buf, int k0) {
        uint32_t aoff = smb + buf * STAGE_BYTES;
        uint32_t boff = aoff + A_STAGE;
#pragma unroll
        for (int l = 0; l < 2; l++) {
            int idx = tid + l * 512;
            int kr  = idx >> 6;
            int u   = idx & 63;
            cp16(boff + (kr * 520 + u * 8) * 2,
                 Bp + (size_t)(k0 + kr) * GATE3 + coff + u * 8);
        }
        if (tid < 128) {
            int r = tid >> 1;
            int u = tid & 1;
            cp16(aoff + (r * 24 + u * 8) * 2,
                 Ap + (size_t)(rowBase + r) * HID + k0 + u * 8);
        }
    };

    load1(0, 0);  cp_commit();
    load1(1, 16); cp_commit();
    load1(2, 32); cp_commit();

#pragma unroll 1
    for (int c = 0; c < NC; c++) {
        asm volatile("cp.async.wait_group 2;\n" ::: "memory");
        __syncthreads();
        if (c + 3 < NC) load1((c + 3) & 3, (c + 3) * 16);
        cp_commit();

        uint32_t aoff = smb + (c & 3) * STAGE_BYTES;
        uint32_t boff = aoff + A_STAGE;

        unsigned af0[4];
        {
            uint32_t ad = aoff + ((wr * 16 + (lane & 15)) * 24 + (lane >> 4) * 8) * 2;
            ldsm4(af0, ad);
        }
#pragma unroll
        for (int g2 = 0; g2 < 4; g2++) {
            unsigned b0[4], b1[4];
            uint32_t bd0 = boff + ((lane & 15) * 520 + wc * 128 + (g2 * 2) * 16 + (lane >> 4) * 8) * 2;
            ldsm4t(b0, bd0);
            ldsm4t(b1, bd0 + 32);
            int j0 = g2 * 4;
            mma16816(acc[j0 + 0], af0, b0);
            mma16816(acc[j0 + 1], af0, b0 + 2);
            mma16816(acc[j0 + 2], af0, b1);
            mma16816(acc[j0 + 3], af0, b1 + 2);
        }
    }

#pragma unroll
    for (int h = 0; h < 2; h++) {
        size_t base = (size_t)(rowBase + wr * 16 + h * 8 + g) * GATE3 + coff;
#pragma unroll
        for (int jt = 0; jt < 16; jt++) {
            int cl = wc * 128 + jt * 8 + 2 * tig;
            float2 v;
            v.x = acc[jt][h * 2 + 0];
            v.y = acc[jt][h * 2 + 1];
            *reinterpret_cast<float2*>(out + base + cl) = v;
        }
    }
}

// ---------------- GRU gate fusion (sums 3 GH plane partials + b_hh) ----------
__global__ void gates_kernel(int t, const float* __restrict__ hp,
                             const float* __restrict__ bhh,
                             float* __restrict__ hn,
                             bf16* __restrict__ hnh, bf16* __restrict__ hnl,
                             float* __restrict__ dout) {
    int idx = blockIdx.x * blockDim.x + threadIdx.x;
    if (idx >= BATCH * HID) return;
    int r = idx >> 9;
    int c = idx & 511;
    size_t gib = ((size_t)t * BATCH + r) * GATE3;
    size_t ghb = (size_t)r * GATE3;
    const size_t PS = (size_t)BATCH * GATE3;
    float ir = g_GI[gib + c], iz = g_GI[gib + c + HID], in_ = g_GI[gib + c + 2 * HID];
    float hr = g_GH[ghb + c]           + g_GH[PS + ghb + c]           + g_GH[2 * PS + ghb + c]           + bhh[c];
    float hz = g_GH[ghb + c + HID]     + g_GH[PS + ghb + c + HID]     + g_GH[2 * PS + ghb + c + HID]     + bhh[c + HID];
    float hnn= g_GH[ghb + c + 2 * HID] + g_GH[PS + ghb + c + 2 * HID] + g_GH[2 * PS + ghb + c + 2 * HID] + bhh[c + 2 * HID];
    float rg = 1.f / (1.f + expf(-(ir + hr)));
    float zg = 1.f / (1.f + expf(-(iz + hz)));
    float ng = tanhf(in_ + rg * hnn);
    float h  = hp[idx];
    float v  = (1.f - zg) * ng + zg * h;
    hn[idx] = v;
    bf16 vh = __float2bfloat16(v);
    hnh[idx] = vh;
    hnl[idx] = __float2bfloat16(v - __bfloat162float(vh));
    if (dout) dout[idx] = v;
}

// ---------------- host orchestration ----------------------------------------
extern "C" void kernel_launch(void* const* d_in, const int* in_sizes, int n_in,
                              void* d_out, int out_size) {
    const float* xs       = (const float*)d_in[0];
    const float* obs_W    = (const float*)d_in[1];
    const float* obs_b    = (const float*)d_in[2];
    const float* obs_ln_g = (const float*)d_in[3];
    const float* obs_ln_b = (const float*)d_in[4];
    const float* ode_W1   = (const float*)d_in[5];   // [513,512]
    const float* ode_b1   = (const float*)d_in[6];
    const float* ode_ln1g = (const float*)d_in[7];
    const float* ode_ln1b = (const float*)d_in[8];
    const float* ode_W2   = (const float*)d_in[9];
    const float* ode_b2   = (const float*)d_in[10];
    const float* ode_ln2g = (const float*)d_in[11];
    const float* ode_ln2b = (const float*)d_in[12];
    const float* ode_Wout = (const float*)d_in[13];
    const float* ode_bout = (const float*)d_in[14];
    const float* W_ih     = (const float*)d_in[15];  // [512,1536]
    const float* b_ih     = (const float*)d_in[16];
    const float* W_hh     = (const float*)d_in[17];
    const float* b_hh     = (const float*)d_in[18];

    float *pH, *pKACC, *pGI, *pGH, *pHP0, *pHP1;
    cudaGetSymbolAddress((void**)&pH,    g_H);
    cudaGetSymbolAddress((void**)&pKACC, g_KACC);
    cudaGetSymbolAddress((void**)&pGI,   g_GI);
    cudaGetSymbolAddress((void**)&pGH,   g_GH);
    cudaGetSymbolAddress((void**)&pHP0,  g_HP0);
    cudaGetSymbolAddress((void**)&pHP1,  g_HP1);

    bf16 *pHh, *pHl, *pTh, *pTl, *pZ1h, *pZ1l, *pZ2h, *pZ2l;
    bf16 *pP0h, *pP0l, *pP1h, *pP1l;
    bf16 *pW1h, *pW1l, *pW2h, *pW2l, *pWoh, *pWol, *pWihh, *pWihl, *pWhhh, *pWhhl;
    cudaGetSymbolAddress((void**)&pHh,  g_Hh);   cudaGetSymbolAddress((void**)&pHl,  g_Hl);
    cudaGetSymbolAddress((void**)&pTh,  g_Th);   cudaGetSymbolAddress((void**)&pTl,  g_Tl);
    cudaGetSymbolAddress((void**)&pZ1h, g_Z1h);  cudaGetSymbolAddress((void**)&pZ1l, g_Z1l);
    cudaGetSymbolAddress((void**)&pZ2h, g_Z2h);  cudaGetSymbolAddress((void**)&pZ2l, g_Z2l);
    cudaGetSymbolAddress((void**)&pP0h, g_P0h);  cudaGetSymbolAddress((void**)&pP0l, g_P0l);
    cudaGetSymbolAddress((void**)&pP1h, g_P1h);  cudaGetSymbolAddress((void**)&pP1l, g_P1l);
    cudaGetSymbolAddress((void**)&pW1h, g_W1h);  cudaGetSymbolAddress((void**)&pW1l, g_W1l);
    cudaGetSymbolAddress((void**)&pW2h, g_W2h);  cudaGetSymbolAddress((void**)&pW2l, g_W2l);
    cudaGetSymbolAddress((void**)&pWoh, g_Woh);  cudaGetSymbolAddress((void**)&pWol, g_Wol);
    cudaGetSymbolAddress((void**)&pWihh, g_Wih_h); cudaGetSymbolAddress((void**)&pWihl, g_Wih_l);
    cudaGetSymbolAddress((void**)&pWhhh, g_Whh_h); cudaGetSymbolAddress((void**)&pWhhl, g_Whh_l);

    cudaFuncSetAttribute(gemm_mma, cudaFuncAttributeMaxDynamicSharedMemorySize,
                         SMEM_TOTAL_BYTES);
    cudaFuncSetAttribute(gemm_gru, cudaFuncAttributeMaxDynamicSharedMemorySize,
                         SMEM_TOTAL_BYTES);

    {
        int n = HID * HID;
        split_kernel<<<(n + 255) / 256, 256>>>(ode_W1,   pW1h, pW1l, n);
        split_kernel<<<(n + 255) / 256, 256>>>(ode_W2,   pW2h, pW2l, n);
        split_kernel<<<(n + 255) / 256, 256>>>(ode_Wout, pWoh, pWol, n);
        int m = HID * GATE3;
        split_kernel<<<(m + 255) / 256, 256>>>(W_ih, pWihh, pWihl, m);
        split_kernel<<<(m + 255) / 256, 256>>>(W_hh, pWhhh, pWhhl, m);
    }

    zero_hp0_kernel<<<(BATCH * HID + 255) / 256, 256>>>();
    obs_kernel<<<TB, 256>>>(xs, obs_W, obs_b, obs_ln_g, obs_ln_b);

    const float* trow = ode_W1 + (size_t)512 * 512;
    dim3 gOde(TB / 64, 1);
    const size_t SM = SMEM_TOTAL_BYTES;

    for (int s = 0; s < 4; s++) {
        float t0 = s * 0.25f;
        float tv[4] = {t0, t0 + 0.125f, t0 + 0.125f, t0 + 0.25f};
        int   km[4] = {2, 3, 4, 5};
        for (int e = 0; e < 4; e++) {
            const bf16* Ahh = (e == 0) ? pHh : pTh;
            const bf16* All = (e == 0) ? pHl : pTl;
            gemm_mma<<<gOde, 512, SM>>>(Ahh, All, pW1h, pW1l, HID,
                                        ode_b1, trow, tv[e], ode_ln1g, ode_ln1b,
                                        nullptr, 0, pZ1h, pZ1l, nullptr, nullptr, 0);
            gemm_mma<<<gOde, 512, SM>>>(pZ1h, pZ1l, pW2h, pW2l, HID,
                                        ode_b2, nullptr, 0.f, ode_ln2g, ode_ln2b,
                                        nullptr, 0, pZ2h, pZ2l, nullptr, nullptr, 0);
            bf16* oh = (km[e] == 5) ? pHh : pTh;
            bf16* ol = (km[e] == 5) ? pHl : pTl;
            gemm_mma<<<gOde, 512, SM>>>(pZ2h, pZ2l, pWoh, pWol, HID,
                                        ode_bout, nullptr, 0.f, nullptr, nullptr,
                                        nullptr, 0, oh, ol, pH, pKACC, km[e]);
        }
    }

    // gi = h_ode @ W_ih + b_ih for all timesteps
    gemm_mma<<<dim3(TB / 64, 3), 512, SM>>>(pHh, pHl, pWihh, pWihl, GATE3,
                                            b_ih, nullptr, 0.f, nullptr, nullptr,
                                            pGI, GATE3, nullptr, nullptr,
                                            nullptr, nullptr, 1);

    // sequential GRU — dedicated plane-split kernel (144 CTAs = full wave)
    for (int t = 0; t < T_STEPS; t++) {
        float* hp = (t & 1) ? pHP1 : pHP0;
        float* hn = (t & 1) ? pHP0 : pHP1;
        bf16* hph = (t & 1) ? pP1h : pP0h;
        bf16* hpl = (t & 1) ? pP1l : pP0l;
        bf16* hnh = (t & 1) ? pP0h : pP1h;
        bf16* hnl = (t & 1) ? pP0l : pP1l;
        gemm_gru<<<dim3(BATCH / 64, 3, 3), 512, SM>>>(hph, hpl, pWhhh, pWhhl, pGH);
        gates_kernel<<<(BATCH * HID + 255) / 256, 256>>>(
            t, hp, b_hh, hn, hnh, hnl, (t == T_STEPS - 1) ? (float*)d_out : nullptr);
    }
}